// round 3
// baseline (speedup 1.0000x reference)
#include <cuda_runtime.h>
#include <cstdint>

// ---------------- problem constants ----------------
#define E_NUM     8
#define IN_F      2048
#define OUT_F     2048
#define BM        128
#define BN        256
#define BK        32
#define KCH       (IN_F / BK)      // 64
#define NT_TILES  (OUT_F / BN)     // 8
#define MAXMT     136
#define NTH       512              // 16 warps -> 4 per SMSP
#define STAGES    3

#define A_FLOATS     (BM * BK)                 // 4096
#define B_FLOATS     (BN * BK)                 // 8192
#define STAGE_FLOATS (A_FLOATS + B_FLOATS)     // 12288
#define SMEM_BYTES   (STAGES * STAGE_FLOATS * 4)  // 147456

// ---------------- ptx helpers (base ISA only) ------------
static __device__ __forceinline__ uint32_t smem_u32(const void* p) {
    uint32_t a;
    asm("{ .reg .u64 t; cvta.to.shared.u64 t, %1; cvt.u32.u64 %0, t; }" : "=r"(a) : "l"(p));
    return a;
}

static __device__ __forceinline__ uint32_t tf32_rna(float f) {
    uint32_t r;
    asm("cvt.rna.tf32.f32 %0, %1;" : "=r"(r) : "f"(f));
    return r;
}

static __device__ __forceinline__ void cp16(uint32_t dst, const void* src, uint32_t srcsz) {
    asm volatile("cp.async.cg.shared.global [%0], [%1], 16, %2;"
                 :: "r"(dst), "l"(src), "r"(srcsz) : "memory");
}

static __device__ __forceinline__ void cp_commit() {
    asm volatile("cp.async.commit_group;" ::: "memory");
}

static __device__ __forceinline__ void cp_wait1() {
    asm volatile("cp.async.wait_group 1;" ::: "memory");
}

static __device__ __forceinline__ void mma8(float* c, const uint32_t* a, const uint32_t* b) {
    asm volatile(
        "mma.sync.aligned.m16n8k8.row.col.f32.tf32.tf32.f32 "
        "{%0,%1,%2,%3}, {%4,%5,%6,%7}, {%8,%9}, {%0,%1,%2,%3};"
        : "+f"(c[0]), "+f"(c[1]), "+f"(c[2]), "+f"(c[3])
        : "r"(a[0]), "r"(a[1]), "r"(a[2]), "r"(a[3]), "r"(b[0]), "r"(b[1]));
}

static __device__ __forceinline__ long long load_off(const int* p, int i, bool is64) {
    if (is64) return ((const long long*)p)[i];
    return (long long)p[i];
}

__global__ void __launch_bounds__(NTH, 1)
moe_mma_kernel(const float* __restrict__ X,
               const int*   __restrict__ offs_raw,
               const float* __restrict__ W,
               const float* __restrict__ Bias,
               float*       __restrict__ Y)
{
    const int tid  = threadIdx.x;
    const int lane = tid & 31;
    const int wid  = tid >> 5;
    const int wm   = wid >> 2;   // 0..3 : 32-row slab
    const int wn   = wid & 3;    // 0..3 : 64-col slab
    const int n0   = blockIdx.x * BN;

    // ---- flat m-tile -> (expert, row range) ----
    const bool is64 = ((offs_raw[1] | offs_raw[3] | offs_raw[5] | offs_raw[7]) == 0);
    int e = -1;
    long long row0 = 0, rend = 0;
    {
        int rem = blockIdx.y;
        long long lo = load_off(offs_raw, 0, is64);
        #pragma unroll
        for (int i = 0; i < E_NUM; i++) {
            long long hi = load_off(offs_raw, i + 1, is64);
            int t = (int)((hi - lo + (BM - 1)) >> 7);
            if (e < 0 && rem < t) { e = i; row0 = lo + ((long long)rem << 7); rend = hi; }
            if (e < 0) rem -= t;
            lo = hi;
        }
    }
    if (e < 0) return;  // surplus CTA, uniform exit
    const int rows = (int)(((rend - row0) < BM) ? (rend - row0) : BM);

    extern __shared__ float smf[];
    const uint32_t smem_base = smem_u32(smf);

    // ---- staging precompute: 512 threads, 8 per row (16B groups) ----
    const int grow = tid >> 3;          // 0..63 base row
    const int gc4  = tid & 7;           // 16B column group
    // XOR-4 swizzle identical to the fragment-side (c ^ ((r&7)*4)) form
    const uint32_t a_sw = (uint32_t)((gc4 * 4) ^ ((grow & 7) * 4));

    // A: 128 rows -> 2 passes of 64
    const float* agp[2]; uint32_t asz[2]; uint32_t asmoff[2];
    #pragma unroll
    for (int p = 0; p < 2; p++) {
        int ar = grow + 64 * p;
        bool v = ar < rows;
        agp[p]    = X + (size_t)(row0 + (v ? ar : 0)) * IN_F + gc4 * 4;
        asz[p]    = v ? 16u : 0u;      // size 0 -> cp.async zero-fill
        asmoff[p] = (uint32_t)(ar * 32) * 4u + a_sw * 4u;
    }
    // B: 256 rows -> 4 passes of 64
    const float* bgp[4]; uint32_t bsmoff[4];
    #pragma unroll
    for (int p = 0; p < 4; p++) {
        int br = grow + 64 * p;
        bgp[p]    = W + ((size_t)e * OUT_F + n0 + br) * IN_F + gc4 * 4;
        bsmoff[p] = (uint32_t)(br * 32) * 4u + a_sw * 4u;
    }

    // ---- accumulators: warp tile 32x64 -> 2 x 8 x (16x8) mma tiles ----
    float acc[2][8][4];
    #pragma unroll
    for (int mi = 0; mi < 2; mi++)
        #pragma unroll
        for (int nj = 0; nj < 8; nj++)
            #pragma unroll
            for (int q = 0; q < 4; q++) acc[mi][nj][q] = 0.0f;

    auto load_stage = [&](int kc, int sidx) {
        if (kc < KCH) {
            uint32_t ab = smem_base + (uint32_t)sidx * (STAGE_FLOATS * 4);
            uint32_t bb = ab + A_FLOATS * 4;
            const uint32_t koff = (uint32_t)kc * BK;
            #pragma unroll
            for (int p = 0; p < 2; p++) cp16(ab + asmoff[p], agp[p] + koff, asz[p]);
            #pragma unroll
            for (int p = 0; p < 4; p++) cp16(bb + bsmoff[p], bgp[p] + koff, 16u);
        }
        cp_commit();
    };

    const int lr  = lane >> 2;               // 0..7
    const int lc  = lane & 3;                // 0..3
    const uint32_t fsw = (uint32_t)(lr * 4); // fragment swizzle term

    load_stage(0, 0);
    load_stage(1, 1);

    int sidx = 0;                 // stage of current kc
    int pidx = 2;                 // stage to prefetch into (kc+2)
    for (int kc = 0; kc < KCH; kc++) {
        cp_wait1();
        __syncthreads();
        load_stage(kc + 2, pidx);

        const float* As = smf + sidx * STAGE_FLOATS;
        const float* Bs = As + A_FLOATS;

        #pragma unroll
        for (int ks = 0; ks < 4; ks++) {
            const int k0 = ks * 8;
            uint32_t a[2][4], b[8][2];
            #pragma unroll
            for (int mi = 0; mi < 2; mi++) {
                int r = wm * 32 + mi * 16 + lr;
                a[mi][0] = tf32_rna(As[r * 32       + ((k0 + lc)     ^ fsw)]);
                a[mi][1] = tf32_rna(As[(r + 8) * 32 + ((k0 + lc)     ^ fsw)]);
                a[mi][2] = tf32_rna(As[r * 32       + ((k0 + 4 + lc) ^ fsw)]);
                a[mi][3] = tf32_rna(As[(r + 8) * 32 + ((k0 + 4 + lc) ^ fsw)]);
            }
            #pragma unroll
            for (int nj = 0; nj < 8; nj++) {
                int n = wn * 64 + nj * 8 + lr;
                b[nj][0] = tf32_rna(Bs[n * 32 + ((k0 + lc)     ^ fsw)]);
                b[nj][1] = tf32_rna(Bs[n * 32 + ((k0 + 4 + lc) ^ fsw)]);
            }
            #pragma unroll
            for (int nj = 0; nj < 8; nj++)
                #pragma unroll
                for (int mi = 0; mi < 2; mi++)
                    mma8(acc[mi][nj], a[mi], b[nj]);
        }

        sidx = (sidx == STAGES - 1) ? 0 : sidx + 1;
        pidx = (pidx == STAGES - 1) ? 0 : pidx + 1;
    }

    // ---- epilogue: bias add + float2 stores ----
    #pragma unroll
    for (int nj = 0; nj < 8; nj++) {
        const int gc = n0 + wn * 64 + nj * 8 + lc * 2;
        const float b0 = __ldg(Bias + (size_t)e * OUT_F + gc);
        const float b1 = __ldg(Bias + (size_t)e * OUT_F + gc + 1);
        #pragma unroll
        for (int mi = 0; mi < 2; mi++) {
            const int gr = wm * 32 + mi * 16 + lr;
            if (gr < rows) {
                float2 v;
                v.x = acc[mi][nj][0] + b0;
                v.y = acc[mi][nj][1] + b1;
                *(float2*)(Y + (size_t)(row0 + gr) * OUT_F + gc) = v;
            }
            if (gr + 8 < rows) {
                float2 v;
                v.x = acc[mi][nj][2] + b0;
                v.y = acc[mi][nj][3] + b1;
                *(float2*)(Y + (size_t)(row0 + gr + 8) * OUT_F + gc) = v;
            }
        }
    }
}

extern "C" void kernel_launch(void* const* d_in, const int* in_sizes, int n_in,
                              void* d_out, int out_size) {
    const float* X    = (const float*)d_in[0];
    const int*   offs = (const int*)d_in[1];
    const float* W    = (const float*)d_in[2];
    const float* Bias = (const float*)d_in[3];
    float*       Y    = (float*)d_out;

    cudaFuncSetAttribute(moe_mma_kernel,
                         cudaFuncAttributeMaxDynamicSharedMemorySize, SMEM_BYTES);
    dim3 grid(NT_TILES, MAXMT);
    moe_mma_kernel<<<grid, NTH, SMEM_BYTES>>>(X, offs, W, Bias, Y);
}

// round 4
// speedup vs baseline: 1.1479x; 1.1479x over previous
#include <cuda_runtime.h>
#include <cstdint>

// ---------------- problem constants ----------------
#define E_NUM     8
#define IN_F      2048
#define OUT_F     2048
#define BM        128
#define BN        256
#define BK        32
#define KCH       (IN_F / BK)      // 64
#define NT_TILES  (OUT_F / BN)     // 8
#define MAXMT     136
#define NTH       256              // 8 warps, 64x64 warp tiles (best known)
#define STAGES    3

#define A_FLOATS     (BM * BK)                 // 4096
#define B_FLOATS     (BN * BK)                 // 8192
#define STAGE_FLOATS (A_FLOATS + B_FLOATS)     // 12288
#define SMEM_BYTES   (STAGES * STAGE_FLOATS * 4)  // 147456

// ---------------- ptx helpers (base ISA only) ------------
static __device__ __forceinline__ uint32_t smem_u32(const void* p) {
    uint32_t a;
    asm("{ .reg .u64 t; cvta.to.shared.u64 t, %1; cvt.u32.u64 %0, t; }" : "=r"(a) : "l"(p));
    return a;
}

static __device__ __forceinline__ uint32_t tf32_rna(float f) {
    uint32_t r;
    asm("cvt.rna.tf32.f32 %0, %1;" : "=r"(r) : "f"(f));
    return r;
}

static __device__ __forceinline__ void cp16(uint32_t dst, const void* src, uint32_t srcsz) {
    asm volatile("cp.async.cg.shared.global [%0], [%1], 16, %2;"
                 :: "r"(dst), "l"(src), "r"(srcsz) : "memory");
}

static __device__ __forceinline__ void cp_commit() {
    asm volatile("cp.async.commit_group;" ::: "memory");
}

static __device__ __forceinline__ void cp_wait1() {
    asm volatile("cp.async.wait_group 1;" ::: "memory");
}

static __device__ __forceinline__ void mma8(float* c, const uint32_t* a, const uint32_t* b) {
    asm volatile(
        "mma.sync.aligned.m16n8k8.row.col.f32.tf32.tf32.f32 "
        "{%0,%1,%2,%3}, {%4,%5,%6,%7}, {%8,%9}, {%0,%1,%2,%3};"
        : "+f"(c[0]), "+f"(c[1]), "+f"(c[2]), "+f"(c[3])
        : "r"(a[0]), "r"(a[1]), "r"(a[2]), "r"(a[3]), "r"(b[0]), "r"(b[1]));
}

static __device__ __forceinline__ long long load_off(const int* p, int i, bool is64) {
    if (is64) return ((const long long*)p)[i];
    return (long long)p[i];
}

__global__ void __launch_bounds__(NTH, 1)
moe_mma_kernel(const float* __restrict__ X,
               const int*   __restrict__ offs_raw,
               const float* __restrict__ W,
               const float* __restrict__ Bias,
               float*       __restrict__ Y)
{
    const int tid  = threadIdx.x;
    const int lane = tid & 31;
    const int wid  = tid >> 5;
    const int wm   = wid >> 2;   // 0..1 : 64-row slab
    const int wn   = wid & 3;    // 0..3 : 64-col slab
    const int n0   = blockIdx.x * BN;

    // ---- flat m-tile -> (expert, row range) ----
    const bool is64 = ((offs_raw[1] | offs_raw[3] | offs_raw[5] | offs_raw[7]) == 0);
    int e = -1;
    long long row0 = 0, rend = 0;
    {
        int rem = blockIdx.y;
        long long lo = load_off(offs_raw, 0, is64);
        #pragma unroll
        for (int i = 0; i < E_NUM; i++) {
            long long hi = load_off(offs_raw, i + 1, is64);
            int t = (int)((hi - lo + (BM - 1)) >> 7);
            if (e < 0 && rem < t) { e = i; row0 = lo + ((long long)rem << 7); rend = hi; }
            if (e < 0) rem -= t;
            lo = hi;
        }
    }
    if (e < 0) return;  // surplus CTA, uniform exit
    const int rows = (int)(((rend - row0) < BM) ? (rend - row0) : BM);

    extern __shared__ float smf[];
    const uint32_t smem_base = smem_u32(smf);

    // ---- staging precompute (lane-constant XOR-4 swizzle) ----
    const int grow = tid >> 3;          // 0..31 base row
    const int gc4  = tid & 7;           // 16B column group
    const uint32_t a_sw = (uint32_t)((gc4 * 4) ^ ((grow & 7) * 4));

    const float* agp[4]; uint32_t asz[4]; uint32_t asmoff[4];
    #pragma unroll
    for (int p = 0; p < 4; p++) {
        int ar = grow + 32 * p;
        bool v = ar < rows;
        agp[p]    = X + (size_t)(row0 + (v ? ar : 0)) * IN_F + gc4 * 4;
        asz[p]    = v ? 16u : 0u;
        asmoff[p] = (uint32_t)(ar * 32) * 4u + a_sw * 4u;
    }
    const float* bgp[8]; uint32_t bsmoff[8];
    #pragma unroll
    for (int p = 0; p < 8; p++) {
        int br = grow + 32 * p;
        bgp[p]    = W + ((size_t)e * OUT_F + n0 + br) * IN_F + gc4 * 4;
        bsmoff[p] = (uint32_t)(br * 32) * 4u + a_sw * 4u;
    }

    // ---- accumulators: warp tile 64x64 ----
    float acc[4][8][4];
    #pragma unroll
    for (int mi = 0; mi < 4; mi++)
        #pragma unroll
        for (int nj = 0; nj < 8; nj++)
            #pragma unroll
            for (int q = 0; q < 4; q++) acc[mi][nj][q] = 0.0f;

    auto load_stage = [&](int kc, int sidx) {
        if (kc < KCH) {
            uint32_t ab = smem_base + (uint32_t)sidx * (STAGE_FLOATS * 4);
            uint32_t bb = ab + A_FLOATS * 4;
            const uint32_t koff = (uint32_t)kc * BK;
            #pragma unroll
            for (int p = 0; p < 4; p++) cp16(ab + asmoff[p], agp[p] + koff, asz[p]);
            #pragma unroll
            for (int p = 0; p < 8; p++) cp16(bb + bsmoff[p], bgp[p] + koff, 16u);
        }
        cp_commit();
    };

    const int lr  = lane >> 2;               // 0..7
    const int lc  = lane & 3;                // 0..3
    const uint32_t fsw = (uint32_t)(lr * 4); // fragment swizzle term

    load_stage(0, 0);
    load_stage(1, 1);

    // double-buffered fragment registers
    uint32_t af[2][4][4], bf[2][8][2];

    int sidx = 0, pidx = 2;
    for (int kc = 0; kc < KCH; kc++) {
        cp_wait1();
        __syncthreads();
        load_stage(kc + 2, pidx);

        const float* As = smf + sidx * STAGE_FLOATS;
        const float* Bs = As + A_FLOATS;

        // fragment loader for one k-step into buffer bi
        auto load_frags = [&](int ks, int bi) {
            const int k0 = ks * 8;
            #pragma unroll
            for (int mi = 0; mi < 4; mi++) {
                int r = wm * 64 + mi * 16 + lr;
                af[bi][mi][0] = tf32_rna(As[r * 32       + ((k0 + lc)     ^ fsw)]);
                af[bi][mi][1] = tf32_rna(As[(r + 8) * 32 + ((k0 + lc)     ^ fsw)]);
                af[bi][mi][2] = tf32_rna(As[r * 32       + ((k0 + 4 + lc) ^ fsw)]);
                af[bi][mi][3] = tf32_rna(As[(r + 8) * 32 + ((k0 + 4 + lc) ^ fsw)]);
            }
            #pragma unroll
            for (int nj = 0; nj < 8; nj++) {
                int n = wn * 64 + nj * 8 + lr;
                bf[bi][nj][0] = tf32_rna(Bs[n * 32 + ((k0 + lc)     ^ fsw)]);
                bf[bi][nj][1] = tf32_rna(Bs[n * 32 + ((k0 + 4 + lc) ^ fsw)]);
            }
        };

        load_frags(0, 0);
        #pragma unroll
        for (int ks = 0; ks < 4; ks++) {
            const int cur = ks & 1;
            if (ks < 3) load_frags(ks + 1, cur ^ 1);   // overlap next-step LDS/CVT with MMAs
            #pragma unroll
            for (int mi = 0; mi < 4; mi++)
                #pragma unroll
                for (int nj = 0; nj < 8; nj++)
                    mma8(acc[mi][nj], af[cur][mi], bf[cur][nj]);
        }

        sidx = (sidx == STAGES - 1) ? 0 : sidx + 1;
        pidx = (pidx == STAGES - 1) ? 0 : pidx + 1;
    }

    // ---- epilogue: bias add + float2 stores ----
    #pragma unroll
    for (int nj = 0; nj < 8; nj++) {
        const int gc = n0 + wn * 64 + nj * 8 + lc * 2;
        const float b0 = __ldg(Bias + (size_t)e * OUT_F + gc);
        const float b1 = __ldg(Bias + (size_t)e * OUT_F + gc + 1);
        #pragma unroll
        for (int mi = 0; mi < 4; mi++) {
            const int gr = wm * 64 + mi * 16 + lr;
            if (gr < rows) {
                float2 v;
                v.x = acc[mi][nj][0] + b0;
                v.y = acc[mi][nj][1] + b1;
                *(float2*)(Y + (size_t)(row0 + gr) * OUT_F + gc) = v;
            }
            if (gr + 8 < rows) {
                float2 v;
                v.x = acc[mi][nj][2] + b0;
                v.y = acc[mi][nj][3] + b1;
                *(float2*)(Y + (size_t)(row0 + gr + 8) * OUT_F + gc) = v;
            }
        }
    }
}

extern "C" void kernel_launch(void* const* d_in, const int* in_sizes, int n_in,
                              void* d_out, int out_size) {
    const float* X    = (const float*)d_in[0];
    const int*   offs = (const int*)d_in[1];
    const float* W    = (const float*)d_in[2];
    const float* Bias = (const float*)d_in[3];
    float*       Y    = (float*)d_out;

    cudaFuncSetAttribute(moe_mma_kernel,
                         cudaFuncAttributeMaxDynamicSharedMemorySize, SMEM_BYTES);
    dim3 grid(NT_TILES, MAXMT);
    moe_mma_kernel<<<grid, NTH, SMEM_BYTES>>>(X, offs, W, Bias, Y);
}